// round 12
// baseline (speedup 1.0000x reference)
#include <cuda_runtime.h>
#include <cuda_fp16.h>
#include <cstdint>
#include <cstddef>

// Problem constants
#define BB    4
#define CIN   256
#define HH    56
#define WW    56
#define COUT  256
#define KK9   9
#define OCH   18
#define P     (HH*WW)     // 3136
#define NTOT  (BB*P)      // 12544
#define KDIM  (CIN*KK9)   // 2304

#define NCHUNK 16
#define CCH    (CIN/NCHUNK)   // 16

// GEMM tiling (fp16 single pass): BM=128, BN=64, BK=64,
// 2 warps (64 thr), warp tile 64x64 (2M x 1N)
#define BM   128
#define BN   64
#define BK   64
#define NKC  (KDIM/BK)    // 36

// padded smem rows (bytes): 64 fp16 = 128B data + 16B pad
#define A_ROWB 144
#define B_ROWB 144
#define A_PLANE (BM*A_ROWB)          // 18432
#define B_PLANE (BK*B_ROWB)          // 9216
#define B_OFF   A_PLANE
#define BUF_BYTES (A_PLANE+B_PLANE)  // 27648
#define SMEM_TOTAL (2*BUF_BYTES)     // 55296 -> 4 CTAs/SM smem-wise

// offconv strips
#define SY_N  (HH/4)
#define STRIPS (BB*SY_N*WW)

// Scratch (device globals)
__device__ __align__(16) float g_OffP[NCHUNK * BB * OCH * P];
__device__ __align__(16) __half g_S[(size_t)KDIM * NTOT];   // fp16 samples
__device__ __align__(16) __half g_W[COUT * KDIM];           // fp16 weights

// ---------------------------------------------------------------------------
// helpers
// ---------------------------------------------------------------------------
__device__ __forceinline__ uint32_t smem_u32(const void* p) {
    uint32_t a;
    asm("{ .reg .u64 t; cvta.to.shared.u64 t, %1; cvt.u32.u64 %0, t; }" : "=r"(a) : "l"(p));
    return a;
}
__device__ __forceinline__ void cp16(uint32_t dst, const void* src) {
    asm volatile("cp.async.ca.shared.global [%0], [%1], 16;" :: "r"(dst), "l"(src) : "memory");
}
__device__ __forceinline__ void cp_commit() {
    asm volatile("cp.async.commit_group;" ::: "memory");
}
__device__ __forceinline__ void cp_wait1() {
    asm volatile("cp.async.wait_group 1;" ::: "memory");
}
__device__ __forceinline__ void cp_wait0() {
    asm volatile("cp.async.wait_group 0;" ::: "memory");
}
__device__ __forceinline__ void ldsm_x4(uint32_t* r, uint32_t addr) {
    asm volatile("ldmatrix.sync.aligned.m8n8.x4.shared.b16 {%0,%1,%2,%3}, [%4];"
                 : "=r"(r[0]), "=r"(r[1]), "=r"(r[2]), "=r"(r[3]) : "r"(addr));
}
__device__ __forceinline__ void ldsm_x4t(uint32_t* r, uint32_t addr) {
    asm volatile("ldmatrix.sync.aligned.m8n8.x4.trans.shared.b16 {%0,%1,%2,%3}, [%4];"
                 : "=r"(r[0]), "=r"(r[1]), "=r"(r[2]), "=r"(r[3]) : "r"(addr));
}
__device__ __forceinline__ void mma_f16(float* c, const uint32_t* a, uint32_t b0, uint32_t b1) {
    asm volatile("mma.sync.aligned.m16n8k16.row.col.f32.f16.f16.f32 "
                 "{%0,%1,%2,%3}, {%4,%5,%6,%7}, {%8,%9}, {%0,%1,%2,%3};"
                 : "+f"(c[0]), "+f"(c[1]), "+f"(c[2]), "+f"(c[3])
                 : "r"(a[0]), "r"(a[1]), "r"(a[2]), "r"(a[3]), "r"(b0), "r"(b1));
}

// ---------------------------------------------------------------------------
// Kernel 0: weight -> fp16
// ---------------------------------------------------------------------------
__global__ __launch_bounds__(256) void wconv_kernel(const float* __restrict__ w) {
    int i = blockIdx.x * 256 + threadIdx.x;
    if (i >= COUT * KDIM) return;
    g_W[i] = __float2half_rn(w[i]);
}

// ---------------------------------------------------------------------------
// Kernel 1: offset conv, 4-row strips (verified)
// ---------------------------------------------------------------------------
__global__ __launch_bounds__(256) void offconv_kernel(
    const float* __restrict__ x, const float* __restrict__ off_w,
    const float* __restrict__ off_b)
{
    __shared__ __align__(16) float ws[OCH * CCH * KK9];
    const int tid   = threadIdx.x;
    const int chunk = blockIdx.y;
    const int ci0   = chunk * CCH;

    for (int i = tid; i < OCH * CCH * KK9; i += 256) {
        int oc  = i / (CCH * KK9);
        int rem = i % (CCH * KK9);
        int cl  = rem / KK9;
        int t   = rem % KK9;
        ws[i] = off_w[((size_t)(oc * CIN + ci0 + cl)) * KK9 + t];
    }
    __syncthreads();

    const int id = blockIdx.x * 256 + tid;
    if (id >= STRIPS) return;
    const int b   = id / (SY_N * WW);
    const int s   = id % (SY_N * WW);
    const int sy  = s / WW;
    const int sx  = s % WW;
    const int y0r = sy * 4;

    float acc[OCH][4];
#pragma unroll
    for (int oc = 0; oc < OCH; oc++) {
        float bias = (chunk == 0) ? off_b[oc] : 0.0f;
#pragma unroll
        for (int r = 0; r < 4; r++) acc[oc][r] = bias;
    }

    const float* xb = x + ((size_t)(b * CIN + ci0)) * P;
    for (int cl = 0; cl < CCH; cl++) {
        const float* xc = xb + (size_t)cl * P;
        float v[6][3];
#pragma unroll
        for (int dy = 0; dy < 6; dy++) {
            int y = y0r - 1 + dy;
#pragma unroll
            for (int dx = 0; dx < 3; dx++) {
                int xx = sx - 1 + dx;
                v[dy][dx] = (y >= 0 && y < HH && xx >= 0 && xx < WW)
                          ? xc[y * WW + xx] : 0.0f;
            }
        }
        const float* wsc = ws + cl * KK9;
#pragma unroll
        for (int oc = 0; oc < OCH; oc++) {
            const float* wo = wsc + oc * (CCH * KK9);
#pragma unroll
            for (int t = 0; t < KK9; t++) {
                float w = wo[t];
                int ty = t / 3, tx = t % 3;
#pragma unroll
                for (int r = 0; r < 4; r++)
                    acc[oc][r] = fmaf(v[r + ty][tx], w, acc[oc][r]);
            }
        }
    }

    float* op = g_OffP + (((size_t)chunk * BB + b) * OCH) * P;
#pragma unroll
    for (int oc = 0; oc < OCH; oc++) {
#pragma unroll
        for (int r = 0; r < 4; r++)
            op[(size_t)oc * P + (y0r + r) * WW + sx] = acc[oc][r];
    }
}

// ---------------------------------------------------------------------------
// Kernel 2: bilinear sampling -> fp16 S[k=ci*9+kk][n=b*P+p]
// ---------------------------------------------------------------------------
__global__ __launch_bounds__(256) void sample_kernel(const float* __restrict__ x)
{
    const int tid = threadIdx.x;
    const int p   = blockIdx.x * 256 + tid;
    if (p >= P) return;
    const int b  = blockIdx.y;
    const int kk = blockIdx.z;

    float offy = 0.0f, offx = 0.0f;
#pragma unroll
    for (int c = 0; c < NCHUNK; c++) {
        const float* op = g_OffP + (((size_t)c * BB + b) * OCH + 2 * kk) * P + p;
        offy += op[0];
        offx += op[P];
    }

    const int ho = p / WW;
    const int wo = p % WW;
    const float py = (float)(ho - 1 + kk / 3) + offy;
    const float px = (float)(wo - 1 + kk % 3) + offx;
    const float fy = floorf(py), fx = floorf(px);
    const int y0 = (int)fy, x0 = (int)fx;
    const int y1 = y0 + 1,  x1 = x0 + 1;
    const float ty = py - fy, tx = px - fx;

    float w00 = (1.0f - ty) * (1.0f - tx);
    float w01 = (1.0f - ty) * tx;
    float w10 = ty * (1.0f - tx);
    float w11 = ty * tx;

    const bool vy0 = (y0 >= 0 && y0 < HH), vy1 = (y1 >= 0 && y1 < HH);
    const bool vx0 = (x0 >= 0 && x0 < WW), vx1 = (x1 >= 0 && x1 < WW);
    w00 *= (vy0 && vx0) ? 1.0f : 0.0f;
    w01 *= (vy0 && vx1) ? 1.0f : 0.0f;
    w10 *= (vy1 && vx0) ? 1.0f : 0.0f;
    w11 *= (vy1 && vx1) ? 1.0f : 0.0f;

    const int cy0 = min(max(y0, 0), HH - 1), cy1 = min(max(y1, 0), HH - 1);
    const int cx0 = min(max(x0, 0), WW - 1), cx1 = min(max(x1, 0), WW - 1);
    const int i00 = cy0 * WW + cx0, i01 = cy0 * WW + cx1;
    const int i10 = cy1 * WW + cx0, i11 = cy1 * WW + cx1;

    const float* xb = x + (size_t)b * CIN * P;
    const size_t base = (size_t)kk * NTOT + (size_t)b * P + p;
    const size_t srow = (size_t)KK9 * NTOT;

#pragma unroll 8
    for (int ci = 0; ci < CIN; ci++) {
        const float* xc = xb + (size_t)ci * P;
        float v = w00 * __ldg(xc + i00) + w01 * __ldg(xc + i01)
                + w10 * __ldg(xc + i10) + w11 * __ldg(xc + i11);
        g_S[base + (size_t)ci * srow] = __float2half_rn(v);
    }
}

// ---------------------------------------------------------------------------
// Kernel 3: single-pass fp16 mma.sync GEMM. BK=64, 2-stage, 2 warps,
// warp tile 64x64 -> A fragments read exactly once per chunk.
// ---------------------------------------------------------------------------
__global__ __launch_bounds__(64, 4) void gemm_mma_kernel(float* __restrict__ out)
{
    extern __shared__ char smem[];
    const uint32_t sb = smem_u32(smem);
    const int tid  = threadIdx.x;
    const int wid  = tid >> 5;     // 0..1 -> M halves
    const int lane = tid & 31;
    const int n0   = blockIdx.x * BN;
    const int m0   = blockIdx.y * BM;

    float acc[4][8][4];
#pragma unroll
    for (int i = 0; i < 4; i++)
#pragma unroll
        for (int j = 0; j < 8; j++)
#pragma unroll
            for (int q = 0; q < 4; q++) acc[i][j][q] = 0.0f;

    const __half* pW = g_W + (size_t)m0 * KDIM;
    const __half* pS = g_S + n0;

    // ldmatrix per-thread address components
    const int lrow  = lane & 15;
    const int lhalf = lane >> 4;
    const uint32_t a_base = (uint32_t)(wid * 64 + lrow) * A_ROWB + lhalf * 16;
    const uint32_t b_base = (uint32_t)lrow * B_ROWB + (uint32_t)(lhalf * 8) * 2;

    // stage loader (64 threads): A 128 rows x 8 granules (16/thread),
    // B 64 rows x 8 granules (8/thread)
    auto load_stage = [&](uint32_t st, int k0) {
#pragma unroll
        for (int it = 0; it < 16; it++) {
            int idx = it * 64 + tid;           // 0..1023
            int row = idx >> 3;
            int c   = idx & 7;
            cp16(st + row * A_ROWB + c * 16, pW + (size_t)row * KDIM + k0 + c * 8);
        }
#pragma unroll
        for (int it = 0; it < 8; it++) {
            int idx = it * 64 + tid;           // 0..511
            int row = idx >> 3;
            int c   = idx & 7;
            cp16(st + B_OFF + row * B_ROWB + c * 16, pS + (size_t)(k0 + row) * NTOT + c * 8);
        }
    };

    load_stage(sb, 0);
    cp_commit();

#pragma unroll 1
    for (int kc = 0; kc < NKC; kc++) {
        const uint32_t buf = sb + (uint32_t)(kc & 1) * BUF_BYTES;
        if (kc < NKC - 1) {
            load_stage(sb + (uint32_t)((kc + 1) & 1) * BUF_BYTES, (kc + 1) * BK);
            cp_commit();
            cp_wait1();
        } else {
            cp_wait0();
        }
        __syncthreads();

#pragma unroll
        for (int kk = 0; kk < 4; kk++) {       // four k16 steps per BK=64 chunk
            uint32_t A[4][4], B[4][4];
#pragma unroll
            for (int mt = 0; mt < 4; mt++)
                ldsm_x4(A[mt], buf + a_base + (uint32_t)mt * 16 * A_ROWB + kk * 32);
#pragma unroll
            for (int bq = 0; bq < 4; bq++)     // n16 tiles covering n64
                ldsm_x4t(B[bq], buf + B_OFF + b_base + (uint32_t)kk * 16 * B_ROWB + bq * 32);
#pragma unroll
            for (int mt = 0; mt < 4; mt++) {
#pragma unroll
                for (int bq = 0; bq < 4; bq++) {
#pragma unroll
                    for (int h = 0; h < 2; h++) {
                        int nt = bq * 2 + h;
                        mma_f16(acc[mt][nt], A[mt], B[bq][2*h], B[bq][2*h+1]);
                    }
                }
            }
        }
        __syncthreads();
    }

    const int g = lane >> 2;
    const int t = lane & 3;
    const int bidx = n0 / P;
    const int pofs = n0 % P;
#pragma unroll
    for (int mt = 0; mt < 4; mt++) {
        int mrow = m0 + wid * 64 + mt * 16 + g;
        float* r0 = out + ((size_t)(bidx * COUT + mrow)) * P + pofs;
        float* r1 = r0 + 8 * P;
#pragma unroll
        for (int nt = 0; nt < 8; nt++) {
            int col = nt * 8 + 2 * t;
            *(float2*)(r0 + col) = make_float2(acc[mt][nt][0], acc[mt][nt][1]);
            *(float2*)(r1 + col) = make_float2(acc[mt][nt][2], acc[mt][nt][3]);
        }
    }
}

// ---------------------------------------------------------------------------
extern "C" void kernel_launch(void* const* d_in, const int* in_sizes, int n_in,
                              void* d_out, int out_size)
{
    const float* x     = (const float*)d_in[0];
    const float* wgt   = (const float*)d_in[1];
    const float* off_w = (const float*)d_in[2];
    const float* off_b = (const float*)d_in[3];
    float* out = (float*)d_out;

    cudaFuncSetAttribute(gemm_mma_kernel, cudaFuncAttributeMaxDynamicSharedMemorySize, SMEM_TOTAL);

    wconv_kernel<<<(COUT * KDIM + 255) / 256, 256>>>(wgt);

    dim3 g1((STRIPS + 255) / 256, NCHUNK);
    offconv_kernel<<<g1, 256>>>(x, off_w, off_b);

    dim3 g2((P + 255) / 256, BB, KK9);
    sample_kernel<<<g2, 256>>>(x);

    dim3 g3(NTOT / BN, COUT / BM);
    gemm_mma_kernel<<<g3, 64, SMEM_TOTAL>>>(out);
}

// round 13
// speedup vs baseline: 1.1384x; 1.1384x over previous
#include <cuda_runtime.h>
#include <cuda_fp16.h>
#include <cstdint>
#include <cstddef>

// Problem constants
#define BB    4
#define CIN   256
#define HH    56
#define WW    56
#define COUT  256
#define KK9   9
#define OCH   18
#define P     (HH*WW)     // 3136
#define NTOT  (BB*P)      // 12544
#define KDIM  (CIN*KK9)   // 2304

#define NCHUNK 32
#define CCH    (CIN/NCHUNK)   // 8

// sample ci split
#define CISPL  2
#define CIH    (CIN/CISPL)    // 128

// GEMM tiling (fp16 single pass): BM=128, BN=64, BK=64,
// 4 warps (128 thr), warp tile 64x32 (2M x 2N)  -- round-11 proven config
#define BM   128
#define BN   64
#define BK   64
#define NKC  (KDIM/BK)    // 36

// padded smem rows (bytes): 64 fp16 = 128B data + 16B pad
#define A_ROWB 144
#define B_ROWB 144
#define A_PLANE (BM*A_ROWB)          // 18432
#define B_PLANE (BK*B_ROWB)          // 9216
#define B_OFF   A_PLANE
#define BUF_BYTES (A_PLANE+B_PLANE)  // 27648
#define SMEM_TOTAL (2*BUF_BYTES)     // 55296

// offconv strips
#define SY_N  (HH/4)
#define STRIPS (BB*SY_N*WW)

// Scratch (device globals)
__device__ __align__(16) float g_OffP[NCHUNK * BB * OCH * P];
__device__ __align__(16) __half g_S[(size_t)KDIM * NTOT];   // fp16 samples
__device__ __align__(16) __half g_W[COUT * KDIM];           // fp16 weights

// ---------------------------------------------------------------------------
// helpers
// ---------------------------------------------------------------------------
__device__ __forceinline__ uint32_t smem_u32(const void* p) {
    uint32_t a;
    asm("{ .reg .u64 t; cvta.to.shared.u64 t, %1; cvt.u32.u64 %0, t; }" : "=r"(a) : "l"(p));
    return a;
}
__device__ __forceinline__ void cp16(uint32_t dst, const void* src) {
    asm volatile("cp.async.ca.shared.global [%0], [%1], 16;" :: "r"(dst), "l"(src) : "memory");
}
__device__ __forceinline__ void cp_commit() {
    asm volatile("cp.async.commit_group;" ::: "memory");
}
__device__ __forceinline__ void cp_wait1() {
    asm volatile("cp.async.wait_group 1;" ::: "memory");
}
__device__ __forceinline__ void cp_wait0() {
    asm volatile("cp.async.wait_group 0;" ::: "memory");
}
__device__ __forceinline__ void ldsm_x4(uint32_t* r, uint32_t addr) {
    asm volatile("ldmatrix.sync.aligned.m8n8.x4.shared.b16 {%0,%1,%2,%3}, [%4];"
                 : "=r"(r[0]), "=r"(r[1]), "=r"(r[2]), "=r"(r[3]) : "r"(addr));
}
__device__ __forceinline__ void ldsm_x4t(uint32_t* r, uint32_t addr) {
    asm volatile("ldmatrix.sync.aligned.m8n8.x4.trans.shared.b16 {%0,%1,%2,%3}, [%4];"
                 : "=r"(r[0]), "=r"(r[1]), "=r"(r[2]), "=r"(r[3]) : "r"(addr));
}
__device__ __forceinline__ void mma_f16(float* c, const uint32_t* a, uint32_t b0, uint32_t b1) {
    asm volatile("mma.sync.aligned.m16n8k16.row.col.f32.f16.f16.f32 "
                 "{%0,%1,%2,%3}, {%4,%5,%6,%7}, {%8,%9}, {%0,%1,%2,%3};"
                 : "+f"(c[0]), "+f"(c[1]), "+f"(c[2]), "+f"(c[3])
                 : "r"(a[0]), "r"(a[1]), "r"(a[2]), "r"(a[3]), "r"(b0), "r"(b1));
}

// ---------------------------------------------------------------------------
// Kernel 0: weight -> fp16
// ---------------------------------------------------------------------------
__global__ __launch_bounds__(256) void wconv_kernel(const float* __restrict__ w) {
    int i = blockIdx.x * 256 + threadIdx.x;
    if (i >= COUT * KDIM) return;
    g_W[i] = __float2half_rn(w[i]);
}

// ---------------------------------------------------------------------------
// Kernel 1: offset conv, 4-row strips; NCHUNK=32 for wave balance.
// ---------------------------------------------------------------------------
__global__ __launch_bounds__(256) void offconv_kernel(
    const float* __restrict__ x, const float* __restrict__ off_w,
    const float* __restrict__ off_b)
{
    __shared__ __align__(16) float ws[OCH * CCH * KK9];
    const int tid   = threadIdx.x;
    const int chunk = blockIdx.y;
    const int ci0   = chunk * CCH;

    for (int i = tid; i < OCH * CCH * KK9; i += 256) {
        int oc  = i / (CCH * KK9);
        int rem = i % (CCH * KK9);
        int cl  = rem / KK9;
        int t   = rem % KK9;
        ws[i] = off_w[((size_t)(oc * CIN + ci0 + cl)) * KK9 + t];
    }
    __syncthreads();

    const int id = blockIdx.x * 256 + tid;
    if (id >= STRIPS) return;
    const int b   = id / (SY_N * WW);
    const int s   = id % (SY_N * WW);
    const int sy  = s / WW;
    const int sx  = s % WW;
    const int y0r = sy * 4;

    float acc[OCH][4];
#pragma unroll
    for (int oc = 0; oc < OCH; oc++) {
        float bias = (chunk == 0) ? off_b[oc] : 0.0f;
#pragma unroll
        for (int r = 0; r < 4; r++) acc[oc][r] = bias;
    }

    const float* xb = x + ((size_t)(b * CIN + ci0)) * P;
    for (int cl = 0; cl < CCH; cl++) {
        const float* xc = xb + (size_t)cl * P;
        float v[6][3];
#pragma unroll
        for (int dy = 0; dy < 6; dy++) {
            int y = y0r - 1 + dy;
#pragma unroll
            for (int dx = 0; dx < 3; dx++) {
                int xx = sx - 1 + dx;
                v[dy][dx] = (y >= 0 && y < HH && xx >= 0 && xx < WW)
                          ? xc[y * WW + xx] : 0.0f;
            }
        }
        const float* wsc = ws + cl * KK9;
#pragma unroll
        for (int oc = 0; oc < OCH; oc++) {
            const float* wo = wsc + oc * (CCH * KK9);
#pragma unroll
            for (int t = 0; t < KK9; t++) {
                float w = wo[t];
                int ty = t / 3, tx = t % 3;
#pragma unroll
                for (int r = 0; r < 4; r++)
                    acc[oc][r] = fmaf(v[r + ty][tx], w, acc[oc][r]);
            }
        }
    }

    float* op = g_OffP + (((size_t)chunk * BB + b) * OCH) * P;
#pragma unroll
    for (int oc = 0; oc < OCH; oc++) {
#pragma unroll
        for (int r = 0; r < 4; r++)
            op[(size_t)oc * P + (y0r + r) * WW + sx] = acc[oc][r];
    }
}

// ---------------------------------------------------------------------------
// Kernel 2: bilinear sampling -> fp16 S[k=ci*9+kk][n=b*P+p]
// grid z encodes (kk, ci-half): more blocks for latency hiding.
// ---------------------------------------------------------------------------
__global__ __launch_bounds__(256) void sample_kernel(const float* __restrict__ x)
{
    const int tid = threadIdx.x;
    const int p   = blockIdx.x * 256 + tid;
    if (p >= P) return;
    const int b   = blockIdx.y;
    const int kk  = blockIdx.z / CISPL;
    const int ci0 = (blockIdx.z % CISPL) * CIH;

    float offy = 0.0f, offx = 0.0f;
#pragma unroll
    for (int c = 0; c < NCHUNK; c++) {
        const float* op = g_OffP + (((size_t)c * BB + b) * OCH + 2 * kk) * P + p;
        offy += op[0];
        offx += op[P];
    }

    const int ho = p / WW;
    const int wo = p % WW;
    const float py = (float)(ho - 1 + kk / 3) + offy;
    const float px = (float)(wo - 1 + kk % 3) + offx;
    const float fy = floorf(py), fx = floorf(px);
    const int y0 = (int)fy, x0 = (int)fx;
    const int y1 = y0 + 1,  x1 = x0 + 1;
    const float ty = py - fy, tx = px - fx;

    float w00 = (1.0f - ty) * (1.0f - tx);
    float w01 = (1.0f - ty) * tx;
    float w10 = ty * (1.0f - tx);
    float w11 = ty * tx;

    const bool vy0 = (y0 >= 0 && y0 < HH), vy1 = (y1 >= 0 && y1 < HH);
    const bool vx0 = (x0 >= 0 && x0 < WW), vx1 = (x1 >= 0 && x1 < WW);
    w00 *= (vy0 && vx0) ? 1.0f : 0.0f;
    w01 *= (vy0 && vx1) ? 1.0f : 0.0f;
    w10 *= (vy1 && vx0) ? 1.0f : 0.0f;
    w11 *= (vy1 && vx1) ? 1.0f : 0.0f;

    const int cy0 = min(max(y0, 0), HH - 1), cy1 = min(max(y1, 0), HH - 1);
    const int cx0 = min(max(x0, 0), WW - 1), cx1 = min(max(x1, 0), WW - 1);
    const int i00 = cy0 * WW + cx0, i01 = cy0 * WW + cx1;
    const int i10 = cy1 * WW + cx0, i11 = cy1 * WW + cx1;

    const float* xb = x + ((size_t)(b * CIN + ci0)) * P;
    const size_t base = (size_t)(ci0 * KK9 + kk) * NTOT + (size_t)b * P + p;
    const size_t srow = (size_t)KK9 * NTOT;

#pragma unroll 8
    for (int ci = 0; ci < CIH; ci++) {
        const float* xc = xb + (size_t)ci * P;
        float v = w00 * __ldg(xc + i00) + w01 * __ldg(xc + i01)
                + w10 * __ldg(xc + i10) + w11 * __ldg(xc + i11);
        g_S[base + (size_t)ci * srow] = __float2half_rn(v);
    }
}

// ---------------------------------------------------------------------------
// Kernel 3: single-pass fp16 mma.sync GEMM (round-11 proven config).
// BK=64, 2-stage, 4 warps (128 thr), warp tile 64x32.
// ---------------------------------------------------------------------------
__global__ __launch_bounds__(128, 3) void gemm_mma_kernel(float* __restrict__ out)
{
    extern __shared__ char smem[];
    const uint32_t sb = smem_u32(smem);
    const int tid  = threadIdx.x;
    const int wid  = tid >> 5;
    const int lane = tid & 31;
    const int wm   = wid & 1;      // 2 warps in M
    const int wn   = wid >> 1;     // 2 warps in N
    const int n0   = blockIdx.x * BN;
    const int m0   = blockIdx.y * BM;

    float acc[4][4][4];
#pragma unroll
    for (int i = 0; i < 4; i++)
#pragma unroll
        for (int j = 0; j < 4; j++)
#pragma unroll
            for (int q = 0; q < 4; q++) acc[i][j][q] = 0.0f;

    const __half* pW = g_W + (size_t)m0 * KDIM;
    const __half* pS = g_S + n0;

    const int lrow  = lane & 15;
    const int lhalf = lane >> 4;
    const uint32_t a_base = (uint32_t)(wm * 64 + lrow) * A_ROWB + lhalf * 16;
    const uint32_t b_base = (uint32_t)lrow * B_ROWB + (uint32_t)(wn * 32 + lhalf * 8) * 2;

    auto load_stage = [&](uint32_t st, int k0) {
#pragma unroll
        for (int it = 0; it < 8; it++) {
            int idx = it * 128 + tid;          // 0..1023
            int row = idx >> 3;
            int c   = idx & 7;
            cp16(st + row * A_ROWB + c * 16, pW + (size_t)row * KDIM + k0 + c * 8);
        }
#pragma unroll
        for (int it = 0; it < 4; it++) {
            int idx = it * 128 + tid;          // 0..511
            int row = idx >> 3;
            int c   = idx & 7;
            cp16(st + B_OFF + row * B_ROWB + c * 16, pS + (size_t)(k0 + row) * NTOT + c * 8);
        }
    };

    load_stage(sb, 0);
    cp_commit();

#pragma unroll 1
    for (int kc = 0; kc < NKC; kc++) {
        const uint32_t buf = sb + (uint32_t)(kc & 1) * BUF_BYTES;
        if (kc < NKC - 1) {
            load_stage(sb + (uint32_t)((kc + 1) & 1) * BUF_BYTES, (kc + 1) * BK);
            cp_commit();
            cp_wait1();
        } else {
            cp_wait0();
        }
        __syncthreads();

#pragma unroll
        for (int kk = 0; kk < 4; kk++) {       // four k16 steps per BK=64 chunk
            uint32_t A[4][4], B[2][4];
#pragma unroll
            for (int mt = 0; mt < 4; mt++)
                ldsm_x4(A[mt], buf + a_base + (uint32_t)mt * 16 * A_ROWB + kk * 32);
#pragma unroll
            for (int bq = 0; bq < 2; bq++)
                ldsm_x4t(B[bq], buf + B_OFF + b_base + (uint32_t)kk * 16 * B_ROWB + bq * 32);
#pragma unroll
            for (int mt = 0; mt < 4; mt++) {
#pragma unroll
                for (int bq = 0; bq < 2; bq++) {
#pragma unroll
                    for (int h = 0; h < 2; h++) {
                        int nt = bq * 2 + h;
                        mma_f16(acc[mt][nt], A[mt], B[bq][2*h], B[bq][2*h+1]);
                    }
                }
            }
        }
        __syncthreads();
    }

    const int g = lane >> 2;
    const int t = lane & 3;
    const int bidx = n0 / P;
    const int pofs = n0 % P;
#pragma unroll
    for (int mt = 0; mt < 4; mt++) {
        int mrow = m0 + wm * 64 + mt * 16 + g;
        float* r0 = out + ((size_t)(bidx * COUT + mrow)) * P + pofs;
        float* r1 = r0 + 8 * P;
#pragma unroll
        for (int nt = 0; nt < 4; nt++) {
            int col = wn * 32 + nt * 8 + 2 * t;
            *(float2*)(r0 + col) = make_float2(acc[mt][nt][0], acc[mt][nt][1]);
            *(float2*)(r1 + col) = make_float2(acc[mt][nt][2], acc[mt][nt][3]);
        }
    }
}

// ---------------------------------------------------------------------------
extern "C" void kernel_launch(void* const* d_in, const int* in_sizes, int n_in,
                              void* d_out, int out_size)
{
    const float* x     = (const float*)d_in[0];
    const float* wgt   = (const float*)d_in[1];
    const float* off_w = (const float*)d_in[2];
    const float* off_b = (const float*)d_in[3];
    float* out = (float*)d_out;

    cudaFuncSetAttribute(gemm_mma_kernel, cudaFuncAttributeMaxDynamicSharedMemorySize, SMEM_TOTAL);

    wconv_kernel<<<(COUT * KDIM + 255) / 256, 256>>>(wgt);

    dim3 g1((STRIPS + 255) / 256, NCHUNK);
    offconv_kernel<<<g1, 256>>>(x, off_w, off_b);

    dim3 g2((P + 255) / 256, BB, KK9 * CISPL);
    sample_kernel<<<g2, 256>>>(x);

    dim3 g3(NTOT / BN, COUT / BM);
    gemm_mma_kernel<<<g3, 128, SMEM_TOTAL>>>(out);
}

// round 14
// speedup vs baseline: 1.2099x; 1.0628x over previous
#include <cuda_runtime.h>
#include <cuda_fp16.h>
#include <cstdint>
#include <cstddef>

// Problem constants
#define BB    4
#define CIN   256
#define HH    56
#define WW    56
#define COUT  256
#define KK9   9
#define OCH   18
#define MOFF  32              // padded M for offset GEMM
#define P     (HH*WW)         // 3136
#define NTOT  (BB*P)          // 12544
#define KDIM  (CIN*KK9)       // 2304

// sample / s0 ci split
#define CISPL  2
#define CIH    (CIN/CISPL)    // 128

// Main GEMM tiling (fp16 single pass): round-11/13 proven config
#define BM   128
#define BN   64
#define BK   64
#define NKC  (KDIM/BK)    // 36

#define A_ROWB 144
#define B_ROWB 144
#define A_PLANE (BM*A_ROWB)          // 18432
#define B_PLANE (BK*B_ROWB)          // 9216
#define B_OFF   A_PLANE
#define BUF_BYTES (A_PLANE+B_PLANE)  // 27648
#define SMEM_TOTAL (2*BUF_BYTES)     // 55296

// Offset GEMM tiling: M=32, N=64, K=64
#define OA_PLANE (MOFF*A_ROWB)       // 4608
#define OB_OFF   OA_PLANE
#define OBUF_BYTES (OA_PLANE+B_PLANE) // 13824
#define OSMEM_TOTAL (2*OBUF_BYTES)    // 27648

// Scratch (device globals)
__device__ __align__(16) __half g_S [(size_t)KDIM * NTOT];  // deformed samples
__device__ __align__(16) __half g_S0[(size_t)KDIM * NTOT];  // zero-offset im2col
__device__ __align__(16) __half g_W[COUT * KDIM];
__device__ __align__(16) __half g_Woff[MOFF * KDIM];        // rows 18..31 zero
__device__ __align__(16) float  g_Off[OCH * NTOT];          // final offsets

// ---------------------------------------------------------------------------
// helpers
// ---------------------------------------------------------------------------
__device__ __forceinline__ uint32_t smem_u32(const void* p) {
    uint32_t a;
    asm("{ .reg .u64 t; cvta.to.shared.u64 t, %1; cvt.u32.u64 %0, t; }" : "=r"(a) : "l"(p));
    return a;
}
__device__ __forceinline__ void cp16(uint32_t dst, const void* src) {
    asm volatile("cp.async.ca.shared.global [%0], [%1], 16;" :: "r"(dst), "l"(src) : "memory");
}
__device__ __forceinline__ void cp_commit() {
    asm volatile("cp.async.commit_group;" ::: "memory");
}
__device__ __forceinline__ void cp_wait1() {
    asm volatile("cp.async.wait_group 1;" ::: "memory");
}
__device__ __forceinline__ void cp_wait0() {
    asm volatile("cp.async.wait_group 0;" ::: "memory");
}
__device__ __forceinline__ void ldsm_x4(uint32_t* r, uint32_t addr) {
    asm volatile("ldmatrix.sync.aligned.m8n8.x4.shared.b16 {%0,%1,%2,%3}, [%4];"
                 : "=r"(r[0]), "=r"(r[1]), "=r"(r[2]), "=r"(r[3]) : "r"(addr));
}
__device__ __forceinline__ void ldsm_x4t(uint32_t* r, uint32_t addr) {
    asm volatile("ldmatrix.sync.aligned.m8n8.x4.trans.shared.b16 {%0,%1,%2,%3}, [%4];"
                 : "=r"(r[0]), "=r"(r[1]), "=r"(r[2]), "=r"(r[3]) : "r"(addr));
}
__device__ __forceinline__ void mma_f16(float* c, const uint32_t* a, uint32_t b0, uint32_t b1) {
    asm volatile("mma.sync.aligned.m16n8k16.row.col.f32.f16.f16.f32 "
                 "{%0,%1,%2,%3}, {%4,%5,%6,%7}, {%8,%9}, {%0,%1,%2,%3};"
                 : "+f"(c[0]), "+f"(c[1]), "+f"(c[2]), "+f"(c[3])
                 : "r"(a[0]), "r"(a[1]), "r"(a[2]), "r"(a[3]), "r"(b0), "r"(b1));
}

// ---------------------------------------------------------------------------
// Kernel 0a: main weights -> fp16
// ---------------------------------------------------------------------------
__global__ __launch_bounds__(256) void wconv_kernel(const float* __restrict__ w) {
    int i = blockIdx.x * 256 + threadIdx.x;
    if (i >= COUT * KDIM) return;
    g_W[i] = __float2half_rn(w[i]);
}

// Kernel 0b: offset weights -> fp16, padded to MOFF rows
__global__ __launch_bounds__(256) void wcvt_off_kernel(const float* __restrict__ ow) {
    int i = blockIdx.x * 256 + threadIdx.x;
    if (i >= MOFF * KDIM) return;
    g_Woff[i] = (i < OCH * KDIM) ? __float2half_rn(ow[i]) : __float2half_rn(0.0f);
}

// ---------------------------------------------------------------------------
// Kernel 1: S0 = zero-offset im2col of x, fp16. 2 pixels per thread.
// grid: (ceil(P/2/256), BB, KK9*CISPL), block 256.
// ---------------------------------------------------------------------------
__global__ __launch_bounds__(256) void s0_kernel(const float* __restrict__ x)
{
    const int pp = blockIdx.x * 256 + threadIdx.x;    // pixel pair
    if (pp >= P / 2) return;
    const int b   = blockIdx.y;
    const int kk  = blockIdx.z / CISPL;
    const int ci0 = (blockIdx.z % CISPL) * CIH;

    const int p0 = pp * 2;
    const int ho = p0 / WW;
    const int wo = p0 % WW;           // even; p1 same row
    const int dy = kk / 3 - 1;
    const int dx = kk % 3 - 1;
    const int y  = ho + dy;
    const bool vy  = (y >= 0 && y < HH);
    const int x0c = wo + dx;
    const int x1c = wo + 1 + dx;
    const bool v0 = vy && (x0c >= 0 && x0c < WW);
    const bool v1 = vy && (x1c >= 0 && x1c < WW);
    const int idx0 = (vy ? y * WW : 0) + (v0 ? x0c : 0);
    const int idx1 = (vy ? y * WW : 0) + (v1 ? x1c : 0);

    const float* xb = x + ((size_t)(b * CIN + ci0)) * P;
    __half2* sp = (__half2*)(g_S0 + (size_t)(ci0 * KK9 + kk) * NTOT + (size_t)b * P + p0);
    const size_t srow2 = (size_t)KK9 * NTOT / 2;   // in half2 units

#pragma unroll 8
    for (int ci = 0; ci < CIH; ci++) {
        const float* xc = xb + (size_t)ci * P;
        float a = v0 ? __ldg(xc + idx0) : 0.0f;
        float c = v1 ? __ldg(xc + idx1) : 0.0f;
        sp[(size_t)ci * srow2] = __floats2half2_rn(a, c);
    }
}

// ---------------------------------------------------------------------------
// Kernel 2: offset GEMM: g_Off[oc][n] = Woff[oc][k]*S0[k][n] + off_b[oc]
// M=32(18), N tiles of 64, K=2304. 128 threads, 4 warps each n16.
// ---------------------------------------------------------------------------
__global__ __launch_bounds__(128) void offgemm_kernel(const float* __restrict__ off_b)
{
    extern __shared__ char smem[];
    const uint32_t sb = smem_u32(smem);
    const int tid  = threadIdx.x;
    const int wid  = tid >> 5;     // 0..3 -> n16 tile
    const int lane = tid & 31;
    const int n0   = blockIdx.x * BN;

    float acc[2][2][4];
#pragma unroll
    for (int i = 0; i < 2; i++)
#pragma unroll
        for (int j = 0; j < 2; j++)
#pragma unroll
            for (int q = 0; q < 4; q++) acc[i][j][q] = 0.0f;

    const __half* pS0 = g_S0 + n0;

    const int lrow  = lane & 15;
    const int lhalf = lane >> 4;
    const uint32_t a_base = (uint32_t)lrow * A_ROWB + lhalf * 16;
    const uint32_t b_base = (uint32_t)lrow * B_ROWB + (uint32_t)(wid * 16 + lhalf * 8) * 2;

    auto load_stage = [&](uint32_t st, int k0) {
        // A: 32 rows x 8 granules = 256 (2/thread)
#pragma unroll
        for (int it = 0; it < 2; it++) {
            int idx = it * 128 + tid;
            int row = idx >> 3;
            int c   = idx & 7;
            cp16(st + row * A_ROWB + c * 16, g_Woff + (size_t)row * KDIM + k0 + c * 8);
        }
        // B: 64 rows x 8 granules = 512 (4/thread)
#pragma unroll
        for (int it = 0; it < 4; it++) {
            int idx = it * 128 + tid;
            int row = idx >> 3;
            int c   = idx & 7;
            cp16(st + OB_OFF + row * B_ROWB + c * 16, pS0 + (size_t)(k0 + row) * NTOT + c * 8);
        }
    };

    load_stage(sb, 0);
    cp_commit();

#pragma unroll 1
    for (int kc = 0; kc < NKC; kc++) {
        const uint32_t buf = sb + (uint32_t)(kc & 1) * OBUF_BYTES;
        if (kc < NKC - 1) {
            load_stage(sb + (uint32_t)((kc + 1) & 1) * OBUF_BYTES, (kc + 1) * BK);
            cp_commit();
            cp_wait1();
        } else {
            cp_wait0();
        }
        __syncthreads();

#pragma unroll
        for (int kk = 0; kk < 4; kk++) {
            uint32_t A[2][4], B[4];
#pragma unroll
            for (int mt = 0; mt < 2; mt++)
                ldsm_x4(A[mt], buf + a_base + (uint32_t)mt * 16 * A_ROWB + kk * 32);
            ldsm_x4t(B, buf + OB_OFF + b_base + (uint32_t)kk * 16 * B_ROWB);
#pragma unroll
            for (int mt = 0; mt < 2; mt++)
#pragma unroll
                for (int h = 0; h < 2; h++)
                    mma_f16(acc[mt][h], A[mt], B[2*h], B[2*h+1]);
        }
        __syncthreads();
    }

    const int g = lane >> 2;
    const int t = lane & 3;
#pragma unroll
    for (int mt = 0; mt < 2; mt++) {
        int r0 = mt * 16 + g;
        int r1 = r0 + 8;
        float b0 = (r0 < OCH) ? off_b[r0] : 0.0f;
        float b1 = (r1 < OCH) ? off_b[r1] : 0.0f;
#pragma unroll
        for (int nt = 0; nt < 2; nt++) {
            int col = n0 + wid * 16 + nt * 8 + 2 * t;
            if (r0 < OCH) {
                g_Off[(size_t)r0 * NTOT + col]     = acc[mt][nt][0] + b0;
                g_Off[(size_t)r0 * NTOT + col + 1] = acc[mt][nt][1] + b0;
            }
            if (r1 < OCH) {
                g_Off[(size_t)r1 * NTOT + col]     = acc[mt][nt][2] + b1;
                g_Off[(size_t)r1 * NTOT + col + 1] = acc[mt][nt][3] + b1;
            }
        }
    }
}

// ---------------------------------------------------------------------------
// Kernel 3: bilinear sampling -> fp16 S[k=ci*9+kk][n=b*P+p]
// offsets now read directly (2 loads).
// ---------------------------------------------------------------------------
__global__ __launch_bounds__(256) void sample_kernel(const float* __restrict__ x)
{
    const int tid = threadIdx.x;
    const int p   = blockIdx.x * 256 + tid;
    if (p >= P) return;
    const int b   = blockIdx.y;
    const int kk  = blockIdx.z / CISPL;
    const int ci0 = (blockIdx.z % CISPL) * CIH;

    const int n = b * P + p;
    const float offy = __ldg(g_Off + (size_t)(2 * kk)     * NTOT + n);
    const float offx = __ldg(g_Off + (size_t)(2 * kk + 1) * NTOT + n);

    const int ho = p / WW;
    const int wo = p % WW;
    const float py = (float)(ho - 1 + kk / 3) + offy;
    const float px = (float)(wo - 1 + kk % 3) + offx;
    const float fy = floorf(py), fx = floorf(px);
    const int y0 = (int)fy, x0 = (int)fx;
    const int y1 = y0 + 1,  x1 = x0 + 1;
    const float ty = py - fy, tx = px - fx;

    float w00 = (1.0f - ty) * (1.0f - tx);
    float w01 = (1.0f - ty) * tx;
    float w10 = ty * (1.0f - tx);
    float w11 = ty * tx;

    const bool vy0 = (y0 >= 0 && y0 < HH), vy1 = (y1 >= 0 && y1 < HH);
    const bool vx0 = (x0 >= 0 && x0 < WW), vx1 = (x1 >= 0 && x1 < WW);
    w00 *= (vy0 && vx0) ? 1.0f : 0.0f;
    w01 *= (vy0 && vx1) ? 1.0f : 0.0f;
    w10 *= (vy1 && vx0) ? 1.0f : 0.0f;
    w11 *= (vy1 && vx1) ? 1.0f : 0.0f;

    const int cy0 = min(max(y0, 0), HH - 1), cy1 = min(max(y1, 0), HH - 1);
    const int cx0 = min(max(x0, 0), WW - 1), cx1 = min(max(x1, 0), WW - 1);
    const int i00 = cy0 * WW + cx0, i01 = cy0 * WW + cx1;
    const int i10 = cy1 * WW + cx0, i11 = cy1 * WW + cx1;

    const float* xb = x + ((size_t)(b * CIN + ci0)) * P;
    const size_t base = (size_t)(ci0 * KK9 + kk) * NTOT + (size_t)n;
    const size_t srow = (size_t)KK9 * NTOT;

#pragma unroll 8
    for (int ci = 0; ci < CIH; ci++) {
        const float* xc = xb + (size_t)ci * P;
        float v = w00 * __ldg(xc + i00) + w01 * __ldg(xc + i01)
                + w10 * __ldg(xc + i10) + w11 * __ldg(xc + i11);
        g_S[base + (size_t)ci * srow] = __float2half_rn(v);
    }
}

// ---------------------------------------------------------------------------
// Kernel 4: main fp16 GEMM (round-13 proven config).
// ---------------------------------------------------------------------------
__global__ __launch_bounds__(128, 3) void gemm_mma_kernel(float* __restrict__ out)
{
    extern __shared__ char smem[];
    const uint32_t sb = smem_u32(smem);
    const int tid  = threadIdx.x;
    const int wid  = tid >> 5;
    const int lane = tid & 31;
    const int wm   = wid & 1;
    const int wn   = wid >> 1;
    const int n0   = blockIdx.x * BN;
    const int m0   = blockIdx.y * BM;

    float acc[4][4][4];
#pragma unroll
    for (int i = 0; i < 4; i++)
#pragma unroll
        for (int j = 0; j < 4; j++)
#pragma unroll
            for (int q = 0; q < 4; q++) acc[i][j][q] = 0.0f;

    const __half* pW = g_W + (size_t)m0 * KDIM;
    const __half* pS = g_S + n0;

    const int lrow  = lane & 15;
    const int lhalf = lane >> 4;
    const uint32_t a_base = (uint32_t)(wm * 64 + lrow) * A_ROWB + lhalf * 16;
    const uint32_t b_base = (uint32_t)lrow * B_ROWB + (uint32_t)(wn * 32 + lhalf * 8) * 2;

    auto load_stage = [&](uint32_t st, int k0) {
#pragma unroll
        for (int it = 0; it < 8; it++) {
            int idx = it * 128 + tid;
            int row = idx >> 3;
            int c   = idx & 7;
            cp16(st + row * A_ROWB + c * 16, pW + (size_t)row * KDIM + k0 + c * 8);
        }
#pragma unroll
        for (int it = 0; it < 4; it++) {
            int idx = it * 128 + tid;
            int row = idx >> 3;
            int c   = idx & 7;
            cp16(st + B_OFF + row * B_ROWB + c * 16, pS + (size_t)(k0 + row) * NTOT + c * 8);
        }
    };

    load_stage(sb, 0);
    cp_commit();

#pragma unroll 1
    for (int kc = 0; kc < NKC; kc++) {
        const uint32_t buf = sb + (uint32_t)(kc & 1) * BUF_BYTES;
        if (kc < NKC - 1) {
            load_stage(sb + (uint32_t)((kc + 1) & 1) * BUF_BYTES, (kc + 1) * BK);
            cp_commit();
            cp_wait1();
        } else {
            cp_wait0();
        }
        __syncthreads();

#pragma unroll
        for (int kk = 0; kk < 4; kk++) {
            uint32_t A[4][4], B[2][4];
#pragma unroll
            for (int mt = 0; mt < 4; mt++)
                ldsm_x4(A[mt], buf + a_base + (uint32_t)mt * 16 * A_ROWB + kk * 32);
#pragma unroll
            for (int bq = 0; bq < 2; bq++)
                ldsm_x4t(B[bq], buf + B_OFF + b_base + (uint32_t)kk * 16 * B_ROWB + bq * 32);
#pragma unroll
            for (int mt = 0; mt < 4; mt++) {
#pragma unroll
                for (int bq = 0; bq < 2; bq++) {
#pragma unroll
                    for (int h = 0; h < 2; h++) {
                        int nt = bq * 2 + h;
                        mma_f16(acc[mt][nt], A[mt], B[bq][2*h], B[bq][2*h+1]);
                    }
                }
            }
        }
        __syncthreads();
    }

    const int g = lane >> 2;
    const int t = lane & 3;
    const int bidx = n0 / P;
    const int pofs = n0 % P;
#pragma unroll
    for (int mt = 0; mt < 4; mt++) {
        int mrow = m0 + wm * 64 + mt * 16 + g;
        float* r0 = out + ((size_t)(bidx * COUT + mrow)) * P + pofs;
        float* r1 = r0 + 8 * P;
#pragma unroll
        for (int nt = 0; nt < 4; nt++) {
            int col = wn * 32 + nt * 8 + 2 * t;
            *(float2*)(r0 + col) = make_float2(acc[mt][nt][0], acc[mt][nt][1]);
            *(float2*)(r1 + col) = make_float2(acc[mt][nt][2], acc[mt][nt][3]);
        }
    }
}

// ---------------------------------------------------------------------------
extern "C" void kernel_launch(void* const* d_in, const int* in_sizes, int n_in,
                              void* d_out, int out_size)
{
    const float* x     = (const float*)d_in[0];
    const float* wgt   = (const float*)d_in[1];
    const float* off_w = (const float*)d_in[2];
    const float* off_b = (const float*)d_in[3];
    float* out = (float*)d_out;

    cudaFuncSetAttribute(gemm_mma_kernel, cudaFuncAttributeMaxDynamicSharedMemorySize, SMEM_TOTAL);
    cudaFuncSetAttribute(offgemm_kernel, cudaFuncAttributeMaxDynamicSharedMemorySize, OSMEM_TOTAL);

    wconv_kernel<<<(COUT * KDIM + 255) / 256, 256>>>(wgt);
    wcvt_off_kernel<<<(MOFF * KDIM + 255) / 256, 256>>>(off_w);

    dim3 g0((P / 2 + 255) / 256, BB, KK9 * CISPL);
    s0_kernel<<<g0, 256>>>(x);

    offgemm_kernel<<<NTOT / BN, 128, OSMEM_TOTAL>>>(off_b);

    dim3 g2((P + 255) / 256, BB, KK9 * CISPL);
    sample_kernel<<<g2, 256>>>(x);

    dim3 g3(NTOT / BN, COUT / BM);
    gemm_mma_kernel<<<g3, 128, SMEM_TOTAL>>>(out);
}